// round 2
// baseline (speedup 1.0000x reference)
#include <cuda_runtime.h>
#include <math.h>

// ---------------------------------------------------------------------------
// EnhancedContrastiveLoss — fp32 SIMT v2 (label dtype fix)
//   sim = (e/||e||) (e/||e||)^T / T   fused with exp/top-3/max epilogue.
// Inputs: d_in[0] = embeddings f32[8192,256], d_in[1] = labels (int32 OR int64)
// Output: scalar f32 loss.
// ---------------------------------------------------------------------------

namespace {
constexpr int   NB   = 8192;
constexpr int   ND   = 256;
constexpr float TEMP = 0.07f;
constexpr float MRG  = 0.2f;
constexpr float NEGINF = -1e30f;
// log2(e)/TEMP : exp(dot/T) = exp2(dot * CEXP)
constexpr float CEXP = 20.609929059847869f;

constexpr int BM = 128, BN = 128, BK = 16;
constexpr int TM = 8,  TN = 8;
constexpr int NTHR = 256;                      // 16x16 thread grid
constexpr int SPLITS = 16;                     // column splits
constexpr int COLTILES = NB / BN;              // 64
constexpr int TILES_PER_SPLIT = COLTILES / SPLITS; // 4
constexpr int ROWBLKS = NB / BM;               // 64
constexpr int RED_BLOCKS = 32;                 // 32 x 256 threads = 8192 rows
}

// Static scratch (no allocations allowed).
__device__ float g_en[NB * ND];                // normalized embeddings (8 MB)
__device__ int   g_lab[NB];                    // labels normalized to int32
__device__ float g_part[NB * SPLITS * 6];      // per (row, split): sumAll,sumPos,pmax,t0,t1,t2
__device__ float g_blk[RED_BLOCKS * 5];        // per-block loss partials

__device__ __forceinline__ float ex2f(float x) {
    float y;
    asm("ex2.approx.f32 %0, %1;" : "=f"(y) : "f"(x));
    return y;
}

// Branchless running top-3 (descending t0 >= t1 >= t2). 5 FMNMX.
__device__ __forceinline__ void ins3(float& t0, float& t1, float& t2, float x) {
    float m;
    m = fmaxf(t0, x); x = fminf(t0, x); t0 = m;
    m = fmaxf(t1, x); x = fminf(t1, x); t1 = m;
    t2 = fmaxf(t2, x);
}

// ---------------------------------------------------------------------------
// Kernel 0: normalize labels to int32, auto-detecting int32 vs int64 input.
// If the buffer holds little-endian int64 values in [0, 512), every odd
// 32-bit word of the first 4096 entries is zero. Genuine random int32 labels
// in [0,512) have ~zero probability of 4096 consecutive zeros at odd indices.
// Single CTA — deterministic, graph-capturable, ~microseconds.
// ---------------------------------------------------------------------------
__global__ void klab(const int* __restrict__ lab32) {
    __shared__ int s_nonzero;
    if (threadIdx.x == 0) s_nonzero = 0;
    __syncthreads();
    int acc = 0;
    for (int i = threadIdx.x; i < NB / 2; i += blockDim.x)
        acc |= lab32[2 * i + 1];          // within first 8192 int32 — safe either way
    if (acc) atomicOr(&s_nonzero, 1);
    __syncthreads();
    const bool is64 = (s_nonzero == 0);
    for (int i = threadIdx.x; i < NB; i += blockDim.x)
        g_lab[i] = is64 ? lab32[2 * i] : lab32[i];
}

// ---------------------------------------------------------------------------
// Kernel 1: L2 normalize, one warp per row.
// ---------------------------------------------------------------------------
__global__ void knorm(const float* __restrict__ emb) {
    int gw   = (blockIdx.x * blockDim.x + threadIdx.x) >> 5;
    int lane = threadIdx.x & 31;
    if (gw >= NB) return;
    const float4* src = reinterpret_cast<const float4*>(emb + (size_t)gw * ND);
    float4 v0 = src[lane * 2];
    float4 v1 = src[lane * 2 + 1];
    float ss = v0.x*v0.x + v0.y*v0.y + v0.z*v0.z + v0.w*v0.w
             + v1.x*v1.x + v1.y*v1.y + v1.z*v1.z + v1.w*v1.w;
    #pragma unroll
    for (int o = 16; o > 0; o >>= 1) ss += __shfl_xor_sync(0xffffffffu, ss, o);
    float inv = 1.0f / fmaxf(sqrtf(ss), 1e-12f);
    v0.x *= inv; v0.y *= inv; v0.z *= inv; v0.w *= inv;
    v1.x *= inv; v1.y *= inv; v1.z *= inv; v1.w *= inv;
    float4* dst = reinterpret_cast<float4*>(g_en + (size_t)gw * ND);
    dst[lane * 2]     = v0;
    dst[lane * 2 + 1] = v1;
}

// ---------------------------------------------------------------------------
// Kernel 2: tiled GEMM (dot products) + fused contrastive epilogue.
// Grid: (ROWBLKS, SPLITS). Each CTA: 128 rows x 2048 cols (4 tiles of 128).
// ---------------------------------------------------------------------------
__global__ __launch_bounds__(NTHR) void kmain() {
    __shared__ float As[BK][BM + 4];   // transposed: As[k][row], pad to 132
    __shared__ float Bs[BK][BN + 4];
    __shared__ int   labC[BN];

    const int tid = threadIdx.x;
    const int tx = tid & 15;           // col group
    const int ty = tid >> 4;           // row group
    const int rowBase = blockIdx.x * BM;
    const int split   = blockIdx.y;

    // Per-thread per-row running state (dot units for all maxima).
    float sAll[TM], sPos[TM], pmax[TM], t0[TM], t1[TM], t2[TM];
    int labR[TM];
    #pragma unroll
    for (int r = 0; r < TM; r++) {
        sAll[r] = 0.f; sPos[r] = 0.f; pmax[r] = NEGINF;
        t0[r] = NEGINF; t1[r] = NEGINF; t2[r] = NEGINF;
        labR[r] = g_lab[rowBase + ty * TM + r];
    }

    for (int t = 0; t < TILES_PER_SPLIT; t++) {
        const int colBase = (split * TILES_PER_SPLIT + t) * BN;
        float acc[TM][TN];
        #pragma unroll
        for (int i = 0; i < TM; i++)
            #pragma unroll
            for (int j = 0; j < TN; j++) acc[i][j] = 0.f;

        __syncthreads();                    // previous-iter labC readers done
        if (tid < BN) labC[tid] = g_lab[colBase + tid];

        for (int kc = 0; kc < ND; kc += BK) {
            // Cooperative load of A (row block) and B (col block) k-slices.
            #pragma unroll
            for (int i = 0; i < 2; i++) {
                int idx = tid + i * NTHR;
                int rr = idx >> 2;
                int kq = idx & 3;
                float4 va = *reinterpret_cast<const float4*>(
                    &g_en[(size_t)(rowBase + rr) * ND + kc + kq * 4]);
                As[kq*4+0][rr] = va.x; As[kq*4+1][rr] = va.y;
                As[kq*4+2][rr] = va.z; As[kq*4+3][rr] = va.w;
                float4 vb = *reinterpret_cast<const float4*>(
                    &g_en[(size_t)(colBase + rr) * ND + kc + kq * 4]);
                Bs[kq*4+0][rr] = vb.x; Bs[kq*4+1][rr] = vb.y;
                Bs[kq*4+2][rr] = vb.z; Bs[kq*4+3][rr] = vb.w;
            }
            __syncthreads();
            #pragma unroll
            for (int kk = 0; kk < BK; kk++) {
                float a[TM], b[TN];
                float4 a0 = *reinterpret_cast<const float4*>(&As[kk][ty * TM]);
                float4 a1 = *reinterpret_cast<const float4*>(&As[kk][ty * TM + 4]);
                float4 b0 = *reinterpret_cast<const float4*>(&Bs[kk][tx * TN]);
                float4 b1 = *reinterpret_cast<const float4*>(&Bs[kk][tx * TN + 4]);
                a[0]=a0.x; a[1]=a0.y; a[2]=a0.z; a[3]=a0.w;
                a[4]=a1.x; a[5]=a1.y; a[6]=a1.z; a[7]=a1.w;
                b[0]=b0.x; b[1]=b0.y; b[2]=b0.z; b[3]=b0.w;
                b[4]=b1.x; b[5]=b1.y; b[6]=b1.z; b[7]=b1.w;
                #pragma unroll
                for (int i = 0; i < TM; i++)
                    #pragma unroll
                    for (int j = 0; j < TN; j++)
                        acc[i][j] = fmaf(a[i], b[j], acc[i][j]);
            }
            __syncthreads();
        }

        // Fused epilogue on this 128x128 tile of dots.
        #pragma unroll
        for (int r = 0; r < TM; r++) {
            const int grow = rowBase + ty * TM + r;
            const int lr = labR[r];
            #pragma unroll
            for (int j = 0; j < TN; j++) {
                const int cj = tx * TN + j;
                const int gcol = colBase + cj;
                float d = acc[r][j];
                if (grow != gcol) {                 // exclude diagonal
                    float E = ex2f(d * CEXP);       // exp(dot / T)
                    sAll[r] += E;
                    if (lr == labC[cj]) {
                        sPos[r] += E;
                        pmax[r] = fmaxf(pmax[r], d);
                    } else {
                        ins3(t0[r], t1[r], t2[r], d);
                    }
                }
            }
        }
    }

    // Merge the 16 column-thread partial states per row (half-warp butterfly;
    // tx spans lanes 0..15 / 16..31 of one warp, xor offsets < 16 stay inside).
    #pragma unroll
    for (int r = 0; r < TM; r++) {
        #pragma unroll
        for (int o = 8; o > 0; o >>= 1) {
            sAll[r] += __shfl_xor_sync(0xffffffffu, sAll[r], o);
            sPos[r] += __shfl_xor_sync(0xffffffffu, sPos[r], o);
            pmax[r]  = fmaxf(pmax[r], __shfl_xor_sync(0xffffffffu, pmax[r], o));
            float o0 = __shfl_xor_sync(0xffffffffu, t0[r], o);
            float o1 = __shfl_xor_sync(0xffffffffu, t1[r], o);
            float o2 = __shfl_xor_sync(0xffffffffu, t2[r], o);
            ins3(t0[r], t1[r], t2[r], o0);
            ins3(t0[r], t1[r], t2[r], o1);
            ins3(t0[r], t1[r], t2[r], o2);
        }
    }
    if (tx == 0) {
        #pragma unroll
        for (int r = 0; r < TM; r++) {
            const int grow = rowBase + ty * TM + r;
            float* p = &g_part[(size_t)(grow * SPLITS + split) * 6];
            p[0] = sAll[r]; p[1] = sPos[r]; p[2] = pmax[r];
            p[3] = t0[r];   p[4] = t1[r];   p[5] = t2[r];
        }
    }
}

// ---------------------------------------------------------------------------
// Kernel 3: per-row merge of split partials + per-row loss terms,
// deterministic block reduction to g_blk.
// ---------------------------------------------------------------------------
__global__ void krow() {
    const int row = blockIdx.x * blockDim.x + threadIdx.x;  // 32 x 256 = 8192
    float sA = 0.f, sP = 0.f, pm = NEGINF;
    float t0 = NEGINF, t1 = NEGINF, t2 = NEGINF;
    const float* p = &g_part[(size_t)row * SPLITS * 6];
    #pragma unroll
    for (int s = 0; s < SPLITS; s++) {
        sA += p[0]; sP += p[1];
        pm = fmaxf(pm, p[2]);
        ins3(t0, t1, t2, p[3]);
        ins3(t0, t1, t2, p[4]);
        ins3(t0, t1, t2, p[5]);
        p += 6;
    }

    float basic = 0.f, h = 0.f, m = 0.f, hp = 0.f, v = 0.f;
    const bool hasPos = pm > -1e29f;
    if (hasPos) {
        hp = 1.f;
        basic = -logf(sP / (sA + 1e-10f) + 1e-10f);
        float pms   = pm * (1.f / TEMP);
        float mean3 = (t0 + t1 + t2) * (1.f / (3.f * TEMP));
        h = fmaxf(mean3 - pms + MRG, 0.f);
        if (t0 > -1e29f) {                       // valid = hasPos && hasNeg
            v = 1.f;
            m = fmaxf(t0 * (1.f / TEMP) - pms + MRG, 0.f);
        }
    }

    __shared__ float red[5][8];
    float vals[5] = {basic, h, m, hp, v};
    int lane = threadIdx.x & 31, warp = threadIdx.x >> 5;
    #pragma unroll
    for (int q = 0; q < 5; q++) {
        float x = vals[q];
        #pragma unroll
        for (int o = 16; o > 0; o >>= 1) x += __shfl_xor_sync(0xffffffffu, x, o);
        if (lane == 0) red[q][warp] = x;
    }
    __syncthreads();
    if (warp == 0) {
        #pragma unroll
        for (int q = 0; q < 5; q++) {
            float x = (lane < 8) ? red[q][lane] : 0.f;
            #pragma unroll
            for (int o = 4; o > 0; o >>= 1) x += __shfl_xor_sync(0xffffffffu, x, o);
            if (lane == 0) g_blk[blockIdx.x * 5 + q] = x;
        }
    }
}

// ---------------------------------------------------------------------------
// Kernel 4: final scalar.
// ---------------------------------------------------------------------------
__global__ void kfin(float* __restrict__ out, int n) {
    int lane = threadIdx.x;  // 32 threads, RED_BLOCKS == 32
    float acc[5];
    #pragma unroll
    for (int q = 0; q < 5; q++) {
        float x = g_blk[lane * 5 + q];
        #pragma unroll
        for (int o = 16; o > 0; o >>= 1) x += __shfl_xor_sync(0xffffffffu, x, o);
        acc[q] = x;
    }
    float Bv = acc[0], Hv = acc[1], Mv = acc[2], HP = acc[3], V = acc[4];
    float n_hp = fmaxf(HP, 1.f);
    float n_v  = fmaxf(V, 1.f);
    float margin_loss = (V > 0.f) ? (Mv / n_v) : 0.f;
    float total = Bv / n_hp + 0.5f * (Hv / n_hp) + 0.1f * margin_loss;
    for (int i = lane; i < n; i += 32) out[i] = total;
}

// ---------------------------------------------------------------------------
extern "C" void kernel_launch(void* const* d_in, const int* in_sizes, int n_in,
                              void* d_out, int out_size) {
    const float* emb   = (const float*)d_in[0];
    const int*   lab32 = (const int*)d_in[1];   // int32 or int64 — klab detects
    (void)in_sizes; (void)n_in;

    klab<<<1, 256>>>(lab32);
    knorm<<<NB * 32 / 256, 256>>>(emb);
    dim3 grid(ROWBLKS, SPLITS);
    kmain<<<grid, NTHR>>>();
    krow<<<RED_BLOCKS, 256>>>();
    kfin<<<1, 32>>>((float*)d_out, out_size);
}

// round 4
// speedup vs baseline: 2.8822x; 2.8822x over previous
#include <cuda_runtime.h>
#include <math.h>

// ---------------------------------------------------------------------------
// EnhancedContrastiveLoss — v4: mma.sync tf32 (HMMA) GEMM + fused epilogue.
// (tcgen05 is unavailable: harness PTX target is compute_103 without 'a'.)
// ---------------------------------------------------------------------------

namespace {
constexpr int   NB   = 8192;
constexpr int   ND   = 256;
constexpr float TEMP = 0.07f;
constexpr float MRG  = 0.2f;
constexpr float NEGINF = -1e30f;
constexpr float CEXP = 20.609929059847869f;   // log2(e)/TEMP

constexpr int CSPLITS = 16;                   // column splits (grid.y)
constexpr int TILES   = 4;                    // 128-col tiles per CTA
constexpr int ROWBLKS = NB / 128;             // 64
constexpr int NTHR    = 256;                  // 8 warps: 2 (M) x 4 (N)
constexpr int AST     = 260;                  // A smem row stride (floats), 260%32=4
constexpr int BST     = 36;                   // B smem row stride (floats), 36%32=4
constexpr int RED_BLOCKS = 64;

// dynamic smem layout (bytes)
constexpr int SM_A   = 0;                         // 128 x 260 f32 = 133120
constexpr int SM_B   = 133120;                    // 2 x 128 x 36 f32 = 36864
constexpr int SM_LAB = SM_B + 36864;              // 128 int = 512
constexpr int SM_MRG = SM_LAB + 512;              // 4 x 128 x 6 f32 = 12288
constexpr int SMEM_TOTAL = SM_MRG + 12288;        // 182784
}

__device__ float g_en[NB * ND];                // normalized, tf32-rounded
__device__ int   g_lab[NB];
__device__ float g_part[6 * CSPLITS * NB];     // [q][split][row]
__device__ float g_blk[RED_BLOCKS * 5];

// ----------------------------- helpers ------------------------------------
__device__ __forceinline__ unsigned smem_u32(const void* p) {
    unsigned a;
    asm("{ .reg .u64 t; cvta.to.shared.u64 t, %1; cvt.u32.u64 %0, t; }" : "=r"(a) : "l"(p));
    return a;
}
__device__ __forceinline__ void cpasync16(unsigned dst, const void* src) {
    asm volatile("cp.async.cg.shared.global [%0], [%1], 16;" :: "r"(dst), "l"(src) : "memory");
}
#define CP_COMMIT() asm volatile("cp.async.commit_group;" ::: "memory")
#define CP_WAIT0()  asm volatile("cp.async.wait_group 0;"  ::: "memory")
#define CP_WAIT1()  asm volatile("cp.async.wait_group 1;"  ::: "memory")

__device__ __forceinline__ void mma_tf32(float c[4], const unsigned a[4], const unsigned b[2]) {
    asm volatile(
        "mma.sync.aligned.m16n8k8.row.col.f32.tf32.tf32.f32 "
        "{%0,%1,%2,%3}, {%4,%5,%6,%7}, {%8,%9}, {%0,%1,%2,%3};"
        : "+f"(c[0]), "+f"(c[1]), "+f"(c[2]), "+f"(c[3])
        : "r"(a[0]), "r"(a[1]), "r"(a[2]), "r"(a[3]), "r"(b[0]), "r"(b[1]));
}

__device__ __forceinline__ float ex2f(float x) {
    float y; asm("ex2.approx.f32 %0, %1;" : "=f"(y) : "f"(x)); return y;
}
__device__ __forceinline__ void ins3(float& t0, float& t1, float& t2, float x) {
    float m;
    m = fmaxf(t0, x); x = fminf(t0, x); t0 = m;
    m = fmaxf(t1, x); x = fminf(t1, x); t1 = m;
    t2 = fmaxf(t2, x);
}

// ---------------------------------------------------------------------------
// Kernel 0: label dtype normalize (int64 vs int32 auto-detect)
// ---------------------------------------------------------------------------
__global__ void klab(const int* __restrict__ lab32) {
    __shared__ int s_nz;
    if (threadIdx.x == 0) s_nz = 0;
    __syncthreads();
    int acc = 0;
    for (int i = threadIdx.x; i < NB / 2; i += blockDim.x) acc |= lab32[2 * i + 1];
    if (acc) atomicOr(&s_nz, 1);
    __syncthreads();
    const bool is64 = (s_nz == 0);
    for (int i = threadIdx.x; i < NB; i += blockDim.x)
        g_lab[i] = is64 ? lab32[2 * i] : lab32[i];
}

// ---------------------------------------------------------------------------
// Kernel 1: L2 normalize + round-to-nearest-tf32 (so HMMA truncation is exact)
// ---------------------------------------------------------------------------
__global__ void knorm(const float* __restrict__ emb) {
    int gw   = (blockIdx.x * blockDim.x + threadIdx.x) >> 5;
    int lane = threadIdx.x & 31;
    if (gw >= NB) return;
    const float4* src = reinterpret_cast<const float4*>(emb + (size_t)gw * ND);
    float4 v0 = src[lane * 2];
    float4 v1 = src[lane * 2 + 1];
    float ss = v0.x*v0.x + v0.y*v0.y + v0.z*v0.z + v0.w*v0.w
             + v1.x*v1.x + v1.y*v1.y + v1.z*v1.z + v1.w*v1.w;
    #pragma unroll
    for (int o = 16; o > 0; o >>= 1) ss += __shfl_xor_sync(0xffffffffu, ss, o);
    float inv = 1.0f / fmaxf(sqrtf(ss), 1e-12f);
    float f[8] = {v0.x*inv, v0.y*inv, v0.z*inv, v0.w*inv,
                  v1.x*inv, v1.y*inv, v1.z*inv, v1.w*inv};
    #pragma unroll
    for (int i = 0; i < 8; i++) {
        unsigned b;
        asm("cvt.rna.tf32.f32 %0, %1;" : "=r"(b) : "f"(f[i]));
        f[i] = __uint_as_float(b);
    }
    float4* dst = reinterpret_cast<float4*>(g_en + (size_t)gw * ND);
    dst[lane * 2]     = make_float4(f[0], f[1], f[2], f[3]);
    dst[lane * 2 + 1] = make_float4(f[4], f[5], f[6], f[7]);
}

// ---------------------------------------------------------------------------
// Kernel 2: tf32 mma.sync GEMM + fused contrastive epilogue.
// Grid (64,16), 256 threads. Warp grid 2(M) x 4(N); warp tile 64x32.
// A panel (128x256) persistent in smem; B streamed double-buffered (BK=32).
// ---------------------------------------------------------------------------
__global__ void __launch_bounds__(NTHR, 1) kmain() {
    extern __shared__ char smem[];
    float* As   = (float*)(smem + SM_A);
    float* Bs   = (float*)(smem + SM_B);
    int*   labC = (int*)  (smem + SM_LAB);
    float* mrg  = (float*)(smem + SM_MRG);
    const unsigned sbA = smem_u32(As), sbB = smem_u32(Bs);

    const int tid   = threadIdx.x;
    const int lane  = tid & 31;
    const int wid   = tid >> 5;
    const int warpM = wid >> 2;          // 0..1
    const int warpN = wid & 3;           // 0..3
    const int qrow  = lane >> 2;         // 0..7
    const int qcol  = lane & 3;          // 0..3
    const int rowBase = blockIdx.x * 128;
    const int split   = blockIdx.y;

    // ---- A panel prologue (128 x 256 f32 via cp.async) ----
    {
        const float* srcbase = g_en + (size_t)rowBase * ND;
        #pragma unroll
        for (int i = 0; i < 32; i++) {
            int idx = tid + i * NTHR;            // 0..8191 float4 slots
            int r = idx >> 6, cq = (idx & 63) * 4;
            cpasync16(sbA + (unsigned)(r * AST + cq) * 4u, srcbase + (size_t)r * ND + cq);
        }
        CP_COMMIT();
    }

    // ---- per-thread epilogue state: 8 rows (4 m-frags x 2 halves) ----
    float sAll[8], sPos[8], pmax[8], t0[8], t1[8], t2[8];
    int labR[8];
    #pragma unroll
    for (int st = 0; st < 8; st++) {
        sAll[st] = 0.f; sPos[st] = 0.f; pmax[st] = NEGINF;
        t0[st] = NEGINF; t1[st] = NEGINF; t2[st] = NEGINF;
        labR[st] = g_lab[rowBase + warpM * 64 + (st >> 1) * 16 + (st & 1) * 8 + qrow];
    }

    float acc[4][4][4];

    // B chunk issue: chunk g = tile(g>>3), k-chunk(g&7); 128 x 32 f32
    auto issueB = [&](int g, int stage) {
        const int colBase = (split * TILES + (g >> 3)) * 128;
        const int kc = (g & 7) * 32;
        const int n = tid >> 1, c0 = (tid & 1) * 16;
        const float* src = g_en + (size_t)(colBase + n) * ND + kc + c0;
        unsigned dst = sbB + (unsigned)((stage * 128 + n) * BST + c0) * 4u;
        #pragma unroll
        for (int q = 0; q < 4; q++) cpasync16(dst + q * 16u, src + q * 4);
        CP_COMMIT();
    };

    issueB(0, 0);

    for (int g = 0; g < TILES * 8; g++) {
        const int stage = g & 1;
        if ((g & 7) == 0) {
            if (tid < 128) labC[tid] = g_lab[(split * TILES + (g >> 3)) * 128 + tid];
            #pragma unroll
            for (int i = 0; i < 4; i++)
                #pragma unroll
                for (int j = 0; j < 4; j++)
                    #pragma unroll
                    for (int c = 0; c < 4; c++) acc[i][j][c] = 0.f;
        }
        if (g + 1 < TILES * 8) { issueB(g + 1, stage ^ 1); CP_WAIT1(); }
        else                   { CP_WAIT0(); }
        __syncthreads();

        // ---- compute k-chunk: 4 k-steps of k8 ----
        const float* Apan = As + (g & 7) * 32;
        const float* Bpan = Bs + stage * 128 * BST;
        #pragma unroll
        for (int ks = 0; ks < 4; ks++) {
            const int kb = ks * 8;
            unsigned a[4][4], b[4][2];
            #pragma unroll
            for (int i = 0; i < 4; i++) {
                const float* ap = Apan + (size_t)(warpM * 64 + i * 16 + qrow) * AST + kb + qcol;
                a[i][0] = __float_as_uint(ap[0]);
                a[i][1] = __float_as_uint(ap[8 * AST]);
                a[i][2] = __float_as_uint(ap[4]);
                a[i][3] = __float_as_uint(ap[8 * AST + 4]);
            }
            #pragma unroll
            for (int j = 0; j < 4; j++) {
                const float* bp = Bpan + (size_t)(warpN * 32 + j * 8 + qrow) * BST + kb + qcol;
                b[j][0] = __float_as_uint(bp[0]);
                b[j][1] = __float_as_uint(bp[4]);
            }
            #pragma unroll
            for (int i = 0; i < 4; i++)
                #pragma unroll
                for (int j = 0; j < 4; j++)
                    mma_tf32(acc[i][j], a[i], b[j]);
        }

        // ---- fused epilogue at tile end ----
        if ((g & 7) == 7) {
            const int colBase = (split * TILES + (g >> 3)) * 128;
            #pragma unroll
            for (int i = 0; i < 4; i++) {
                #pragma unroll
                for (int h = 0; h < 2; h++) {
                    const int st = i * 2 + h;
                    const int grow = rowBase + warpM * 64 + i * 16 + h * 8 + qrow;
                    const int lr = labR[st];
                    float lsA = 0.f, lsP = 0.f;
                    #pragma unroll
                    for (int j = 0; j < 4; j++) {
                        #pragma unroll
                        for (int cc = 0; cc < 2; cc++) {
                            const int cl = warpN * 32 + j * 8 + 2 * qcol + cc;
                            const int gcol = colBase + cl;
                            float d = acc[i][j][h * 2 + cc];
                            if (grow != gcol) {
                                float E = ex2f(d * CEXP);
                                lsA += E;
                                if (lr == labC[cl]) {
                                    lsP += E;
                                    pmax[st] = fmaxf(pmax[st], d);
                                } else {
                                    ins3(t0[st], t1[st], t2[st], d);
                                }
                            }
                        }
                    }
                    sAll[st] += lsA; sPos[st] += lsP;
                }
            }
        }
        __syncthreads();
    }

    // ---- merge within quad (lanes sharing qrow: xor 1, 2) ----
    #pragma unroll
    for (int st = 0; st < 8; st++) {
        #pragma unroll
        for (int o = 1; o <= 2; o <<= 1) {
            sAll[st] += __shfl_xor_sync(0xffffffffu, sAll[st], o);
            sPos[st] += __shfl_xor_sync(0xffffffffu, sPos[st], o);
            pmax[st]  = fmaxf(pmax[st], __shfl_xor_sync(0xffffffffu, pmax[st], o));
            float o0 = __shfl_xor_sync(0xffffffffu, t0[st], o);
            float o1 = __shfl_xor_sync(0xffffffffu, t1[st], o);
            float o2 = __shfl_xor_sync(0xffffffffu, t2[st], o);
            ins3(t0[st], t1[st], t2[st], o0);
            ins3(t0[st], t1[st], t2[st], o1);
            ins3(t0[st], t1[st], t2[st], o2);
        }
    }
    if (qcol == 0) {
        #pragma unroll
        for (int st = 0; st < 8; st++) {
            const int rl = warpM * 64 + (st >> 1) * 16 + (st & 1) * 8 + qrow;  // 0..127
            float* p = mrg + (size_t)(warpN * 128 + rl) * 6;
            p[0] = sAll[st]; p[1] = sPos[st]; p[2] = pmax[st];
            p[3] = t0[st];   p[4] = t1[st];   p[5] = t2[st];
        }
    }
    __syncthreads();

    // ---- cross-warpN merge: one thread per row ----
    if (tid < 128) {
        float sA = 0.f, sP = 0.f, pm = NEGINF;
        float u0 = NEGINF, u1 = NEGINF, u2 = NEGINF;
        #pragma unroll
        for (int w = 0; w < 4; w++) {
            const float* p = mrg + (size_t)(w * 128 + tid) * 6;
            sA += p[0]; sP += p[1];
            pm = fmaxf(pm, p[2]);
            ins3(u0, u1, u2, p[3]); ins3(u0, u1, u2, p[4]); ins3(u0, u1, u2, p[5]);
        }
        const int grow = rowBase + tid;
        float out[6] = {sA, sP, pm, u0, u1, u2};
        #pragma unroll
        for (int q = 0; q < 6; q++)
            g_part[(size_t)(q * CSPLITS + split) * NB + grow] = out[q];
    }
}

// ---------------------------------------------------------------------------
// Kernel 3: per-row merge of split partials + loss terms, reduce to g_blk.
// ---------------------------------------------------------------------------
__global__ void krow() {
    const int row = blockIdx.x * blockDim.x + threadIdx.x;  // 64 x 128
    float sA = 0.f, sP = 0.f, pm = NEGINF;
    float t0 = NEGINF, t1 = NEGINF, t2 = NEGINF;
    #pragma unroll
    for (int s = 0; s < CSPLITS; s++) {
        sA += g_part[(size_t)(0 * CSPLITS + s) * NB + row];
        sP += g_part[(size_t)(1 * CSPLITS + s) * NB + row];
        pm  = fmaxf(pm, g_part[(size_t)(2 * CSPLITS + s) * NB + row]);
        ins3(t0, t1, t2, g_part[(size_t)(3 * CSPLITS + s) * NB + row]);
        ins3(t0, t1, t2, g_part[(size_t)(4 * CSPLITS + s) * NB + row]);
        ins3(t0, t1, t2, g_part[(size_t)(5 * CSPLITS + s) * NB + row]);
    }

    float basic = 0.f, h = 0.f, m = 0.f, hp = 0.f, v = 0.f;
    if (pm > -1e29f) {
        hp = 1.f;
        basic = -logf(sP / (sA + 1e-10f) + 1e-10f);
        float pms   = pm * (1.f / TEMP);
        float mean3 = (t0 + t1 + t2) * (1.f / (3.f * TEMP));
        h = fmaxf(mean3 - pms + MRG, 0.f);
        if (t0 > -1e29f) {
            v = 1.f;
            m = fmaxf(t0 * (1.f / TEMP) - pms + MRG, 0.f);
        }
    }

    __shared__ float red[5][4];
    float vals[5] = {basic, h, m, hp, v};
    int lane = threadIdx.x & 31, warp = threadIdx.x >> 5;
    #pragma unroll
    for (int q = 0; q < 5; q++) {
        float x = vals[q];
        #pragma unroll
        for (int o = 16; o > 0; o >>= 1) x += __shfl_xor_sync(0xffffffffu, x, o);
        if (lane == 0) red[q][warp] = x;
    }
    __syncthreads();
    if (warp == 0 && lane == 0) {
        #pragma unroll
        for (int q = 0; q < 5; q++)
            g_blk[blockIdx.x * 5 + q] = red[q][0] + red[q][1] + red[q][2] + red[q][3];
    }
}

// ---------------------------------------------------------------------------
// Kernel 4: final scalar.
// ---------------------------------------------------------------------------
__global__ void kfin(float* __restrict__ out, int n) {
    int lane = threadIdx.x;   // 32 threads
    float acc[5];
    #pragma unroll
    for (int q = 0; q < 5; q++) {
        float x = g_blk[lane * 5 + q] + g_blk[(lane + 32) * 5 + q];
        #pragma unroll
        for (int o = 16; o > 0; o >>= 1) x += __shfl_xor_sync(0xffffffffu, x, o);
        acc[q] = x;
    }
    float Bv = acc[0], Hv = acc[1], Mv = acc[2], HP = acc[3], V = acc[4];
    float n_hp = fmaxf(HP, 1.f);
    float n_v  = fmaxf(V, 1.f);
    float margin_loss = (V > 0.f) ? (Mv / n_v) : 0.f;
    float total = Bv / n_hp + 0.5f * (Hv / n_hp) + 0.1f * margin_loss;
    for (int i = lane; i < n; i += 32) out[i] = total;
}

// ---------------------------------------------------------------------------
extern "C" void kernel_launch(void* const* d_in, const int* in_sizes, int n_in,
                              void* d_out, int out_size) {
    const float* emb   = (const float*)d_in[0];
    const int*   lab32 = (const int*)d_in[1];
    (void)in_sizes; (void)n_in;

    cudaFuncSetAttribute(kmain, cudaFuncAttributeMaxDynamicSharedMemorySize, SMEM_TOTAL);

    klab<<<1, 256>>>(lab32);
    knorm<<<NB * 32 / 256, 256>>>(emb);
    kmain<<<dim3(ROWBLKS, CSPLITS), NTHR, SMEM_TOTAL>>>();
    krow<<<RED_BLOCKS, 128>>>();
    kfin<<<1, 32>>>((float*)d_out, out_size);
}

// round 5
// speedup vs baseline: 5.0790x; 1.7622x over previous
#include <cuda_runtime.h>
#include <math.h>

// ---------------------------------------------------------------------------
// EnhancedContrastiveLoss — v5: symmetric-half tf32 mma.sync + 2 CTAs/SM.
// Only blocks (I,J), I<=J are computed; each off-diagonal block contributes
// a row-view (rows of I, slot J) and a col-view (rows of J, slot I).
// ---------------------------------------------------------------------------

namespace {
constexpr int   NB   = 8192;
constexpr int   ND   = 256;
constexpr float TEMP = 0.07f;
constexpr float MRG  = 0.2f;
constexpr float NEGINF = -1e30f;
constexpr float CEXP = 20.609929059847869f;   // log2(e)/TEMP

constexpr int NBLK  = NB / 128;               // 64 row-blocks
constexpr int NPAIR = NBLK * (NBLK + 1) / 2;  // 2080 CTAs
constexpr int NTHR  = 256;                    // 8 warps: 2(M) x 4(N)
constexpr int OST   = 36;                     // operand smem row stride (floats)
constexpr int DST   = 129;                    // D-tile smem row stride (floats)
constexpr int RED_BLOCKS = 256;

// dynamic smem layout (bytes)
constexpr int SM_OPA  = 0;                        // 2 x 128 x 36 f32 = 36864
constexpr int SM_OPB  = 36864;                    // 2 x 128 x 36 f32 = 36864
constexpr int SM_LABI = 73728;                    // 128 int
constexpr int SM_LABJ = 74240;                    // 128 int
constexpr int SMEM_TOTAL = 74752;
// D tile (128 x 129 f32 = 66048 B) overlays SM_OPA after the GEMM loop.
}

__device__ float g_en[NB * ND];                // normalized, tf32-rounded
__device__ int   g_lab[NB];
__device__ float g_part[6 * NBLK * NB];        // [q][slot][row]  (12.6 MB)
__device__ float g_blk[RED_BLOCKS * 5];

// ----------------------------- helpers ------------------------------------
__device__ __forceinline__ unsigned smem_u32(const void* p) {
    unsigned a;
    asm("{ .reg .u64 t; cvta.to.shared.u64 t, %1; cvt.u32.u64 %0, t; }" : "=r"(a) : "l"(p));
    return a;
}
__device__ __forceinline__ void cpasync16(unsigned dst, const void* src) {
    asm volatile("cp.async.cg.shared.global [%0], [%1], 16;" :: "r"(dst), "l"(src) : "memory");
}
#define CP_COMMIT() asm volatile("cp.async.commit_group;" ::: "memory")
#define CP_WAIT0()  asm volatile("cp.async.wait_group 0;"  ::: "memory")
#define CP_WAIT1()  asm volatile("cp.async.wait_group 1;"  ::: "memory")

__device__ __forceinline__ void mma_tf32(float c[4], const unsigned a[4], const unsigned b[2]) {
    asm volatile(
        "mma.sync.aligned.m16n8k8.row.col.f32.tf32.tf32.f32 "
        "{%0,%1,%2,%3}, {%4,%5,%6,%7}, {%8,%9}, {%0,%1,%2,%3};"
        : "+f"(c[0]), "+f"(c[1]), "+f"(c[2]), "+f"(c[3])
        : "r"(a[0]), "r"(a[1]), "r"(a[2]), "r"(a[3]), "r"(b[0]), "r"(b[1]));
}

__device__ __forceinline__ float ex2f(float x) {
    float y; asm("ex2.approx.f32 %0, %1;" : "=f"(y) : "f"(x)); return y;
}
__device__ __forceinline__ void ins3(float& t0, float& t1, float& t2, float x) {
    float m;
    m = fmaxf(t0, x); x = fminf(t0, x); t0 = m;
    m = fmaxf(t1, x); x = fminf(t1, x); t1 = m;
    t2 = fmaxf(t2, x);
}

// ---------------------------------------------------------------------------
// Kernel 0: label dtype normalize (int64 vs int32 auto-detect)
// ---------------------------------------------------------------------------
__global__ void klab(const int* __restrict__ lab32) {
    __shared__ int s_nz;
    if (threadIdx.x == 0) s_nz = 0;
    __syncthreads();
    int acc = 0;
    for (int i = threadIdx.x; i < NB / 2; i += blockDim.x) acc |= lab32[2 * i + 1];
    if (acc) atomicOr(&s_nz, 1);
    __syncthreads();
    const bool is64 = (s_nz == 0);
    for (int i = threadIdx.x; i < NB; i += blockDim.x)
        g_lab[i] = is64 ? lab32[2 * i] : lab32[i];
}

// ---------------------------------------------------------------------------
// Kernel 1: L2 normalize + round-to-nearest-tf32 (so HMMA truncation is exact)
// ---------------------------------------------------------------------------
__global__ void knorm(const float* __restrict__ emb) {
    int gw   = (blockIdx.x * blockDim.x + threadIdx.x) >> 5;
    int lane = threadIdx.x & 31;
    if (gw >= NB) return;
    const float4* src = reinterpret_cast<const float4*>(emb + (size_t)gw * ND);
    float4 v0 = src[lane * 2];
    float4 v1 = src[lane * 2 + 1];
    float ss = v0.x*v0.x + v0.y*v0.y + v0.z*v0.z + v0.w*v0.w
             + v1.x*v1.x + v1.y*v1.y + v1.z*v1.z + v1.w*v1.w;
    #pragma unroll
    for (int o = 16; o > 0; o >>= 1) ss += __shfl_xor_sync(0xffffffffu, ss, o);
    float inv = 1.0f / fmaxf(sqrtf(ss), 1e-12f);
    float f[8] = {v0.x*inv, v0.y*inv, v0.z*inv, v0.w*inv,
                  v1.x*inv, v1.y*inv, v1.z*inv, v1.w*inv};
    #pragma unroll
    for (int i = 0; i < 8; i++) {
        unsigned b;
        asm("cvt.rna.tf32.f32 %0, %1;" : "=r"(b) : "f"(f[i]));
        f[i] = __uint_as_float(b);
    }
    float4* dst = reinterpret_cast<float4*>(g_en + (size_t)gw * ND);
    dst[lane * 2]     = make_float4(f[0], f[1], f[2], f[3]);
    dst[lane * 2 + 1] = make_float4(f[4], f[5], f[6], f[7]);
}

// ---------------------------------------------------------------------------
// Kernel 2: symmetric-half tf32 GEMM + two-view fused epilogue.
// Grid: 2080 CTAs (one 128x128 block (I,J), I<=J each). 256 threads.
// Both operands streamed double-buffered (128x32 chunks).
// ---------------------------------------------------------------------------
__global__ void __launch_bounds__(NTHR, 2) kmain() {
    extern __shared__ char smem[];
    float* OpA  = (float*)(smem + SM_OPA);
    float* OpB  = (float*)(smem + SM_OPB);
    float* Ds   = (float*)smem;                 // overlays operands post-GEMM
    int*   labI = (int*)(smem + SM_LABI);
    int*   labJ = (int*)(smem + SM_LABJ);
    const unsigned sbA = smem_u32(OpA), sbB = smem_u32(OpB);

    const int tid   = threadIdx.x;
    const int lane  = tid & 31;
    const int wid   = tid >> 5;
    const int warpM = wid >> 2;          // 0..1
    const int warpN = wid & 3;           // 0..3
    const int qrow  = lane >> 2;         // 0..7
    const int qcol  = lane & 3;          // 0..3

    // map linear block id -> (I, J), I <= J
    int I = 0, rem = blockIdx.x;
    while (rem >= NBLK - I) { rem -= NBLK - I; I++; }
    const int J = I + rem;
    const int rowI = I * 128, rowJ = J * 128;
    const bool diag = (I == J);

    // labels into smem
    if (tid < 128) labI[tid] = g_lab[rowI + tid];
    else           labJ[tid - 128] = g_lab[rowJ + tid - 128];

    // chunk issue: A rows of I, B rows of J; 128x32 f32 each, one commit group
    auto issue = [&](int g, int stage) {
        const int kc = g * 32;
        #pragma unroll
        for (int q = 0; q < 4; q++) {
            int idx = tid + q * NTHR;        // 0..1023
            int r = idx >> 3, f = (idx & 7) * 4;
            unsigned off = (unsigned)((stage * 128 + r) * OST + f) * 4u;
            cpasync16(sbA + off, g_en + (size_t)(rowI + r) * ND + kc + f);
            cpasync16(sbB + off, g_en + (size_t)(rowJ + r) * ND + kc + f);
        }
        CP_COMMIT();
    };

    float acc[4][4][4];
    #pragma unroll
    for (int i = 0; i < 4; i++)
        #pragma unroll
        for (int j = 0; j < 4; j++)
            #pragma unroll
            for (int c = 0; c < 4; c++) acc[i][j][c] = 0.f;

    issue(0, 0);

    for (int g = 0; g < 8; g++) {
        const int stage = g & 1;
        if (g < 7) { issue(g + 1, stage ^ 1); CP_WAIT1(); }
        else       { CP_WAIT0(); }
        __syncthreads();                       // chunk g visible to all

        const float* Apan = OpA + stage * 128 * OST;
        const float* Bpan = OpB + stage * 128 * OST;
        #pragma unroll
        for (int ks = 0; ks < 4; ks++) {
            const int kb = ks * 8;
            unsigned a[4][4], b[4][2];
            #pragma unroll
            for (int i = 0; i < 4; i++) {
                const float* ap = Apan + (size_t)(warpM * 64 + i * 16 + qrow) * OST + kb + qcol;
                a[i][0] = __float_as_uint(ap[0]);
                a[i][1] = __float_as_uint(ap[8 * OST]);
                a[i][2] = __float_as_uint(ap[4]);
                a[i][3] = __float_as_uint(ap[8 * OST + 4]);
            }
            #pragma unroll
            for (int j = 0; j < 4; j++) {
                const float* bp = Bpan + (size_t)(warpN * 32 + j * 8 + qrow) * OST + kb + qcol;
                b[j][0] = __float_as_uint(bp[0]);
                b[j][1] = __float_as_uint(bp[4]);
            }
            #pragma unroll
            for (int i = 0; i < 4; i++)
                #pragma unroll
                for (int j = 0; j < 4; j++)
                    mma_tf32(acc[i][j], a[i], b[j]);
        }
        __syncthreads();                       // readers done before overwrite
    }

    // ---- stage D into smem (stride 129) ----
    #pragma unroll
    for (int i = 0; i < 4; i++) {
        #pragma unroll
        for (int j = 0; j < 4; j++) {
            const int rl0 = warpM * 64 + i * 16 + qrow;
            const int cl0 = warpN * 32 + j * 8 + 2 * qcol;
            Ds[(size_t)rl0 * DST + cl0]           = acc[i][j][0];
            Ds[(size_t)rl0 * DST + cl0 + 1]       = acc[i][j][1];
            Ds[(size_t)(rl0 + 8) * DST + cl0]     = acc[i][j][2];
            Ds[(size_t)(rl0 + 8) * DST + cl0 + 1] = acc[i][j][3];
        }
    }
    __syncthreads();

    // ---- two-view epilogue: threads 0-127 row view, 128-255 col view ----
    if (tid < 128) {
        const int rl = tid, grow = rowI + rl;
        const int lr = labI[rl];
        const float* drow = Ds + (size_t)rl * DST;
        float sA = 0.f, sP = 0.f, pm = NEGINF;
        float t0 = NEGINF, t1 = NEGINF, t2 = NEGINF;
        #pragma unroll 4
        for (int c = 0; c < 128; c++) {
            float d = drow[c];
            if (!(diag && c == rl)) {
                float E = ex2f(d * CEXP);
                sA += E;
                if (lr == labJ[c]) { sP += E; pm = fmaxf(pm, d); }
                else ins3(t0, t1, t2, d);
            }
        }
        g_part[(size_t)(0 * NBLK + J) * NB + grow] = sA;
        g_part[(size_t)(1 * NBLK + J) * NB + grow] = sP;
        g_part[(size_t)(2 * NBLK + J) * NB + grow] = pm;
        g_part[(size_t)(3 * NBLK + J) * NB + grow] = t0;
        g_part[(size_t)(4 * NBLK + J) * NB + grow] = t1;
        g_part[(size_t)(5 * NBLK + J) * NB + grow] = t2;
    } else if (!diag) {
        const int cl = tid - 128, gcol = rowJ + cl;
        const int lc = labJ[cl];
        float sA = 0.f, sP = 0.f, pm = NEGINF;
        float t0 = NEGINF, t1 = NEGINF, t2 = NEGINF;
        #pragma unroll 4
        for (int r = 0; r < 128; r++) {
            float d = Ds[(size_t)r * DST + cl];
            float E = ex2f(d * CEXP);
            sA += E;
            if (lc == labI[r]) { sP += E; pm = fmaxf(pm, d); }
            else ins3(t0, t1, t2, d);
        }
        g_part[(size_t)(0 * NBLK + I) * NB + gcol] = sA;
        g_part[(size_t)(1 * NBLK + I) * NB + gcol] = sP;
        g_part[(size_t)(2 * NBLK + I) * NB + gcol] = pm;
        g_part[(size_t)(3 * NBLK + I) * NB + gcol] = t0;
        g_part[(size_t)(4 * NBLK + I) * NB + gcol] = t1;
        g_part[(size_t)(5 * NBLK + I) * NB + gcol] = t2;
    }
}

// ---------------------------------------------------------------------------
// Kernel 3: per-row merge of 64 slot partials (8 threads/row) + loss terms.
// Grid 256 x 256 threads: gid>>3 = row, gid&7 = slot slice.
// ---------------------------------------------------------------------------
__global__ void krow() {
    const int gid = blockIdx.x * blockDim.x + threadIdx.x;
    const int row = gid >> 3;
    const int sl  = (gid & 7) * 8;
    float sA = 0.f, sP = 0.f, pm = NEGINF;
    float t0 = NEGINF, t1 = NEGINF, t2 = NEGINF;
    #pragma unroll
    for (int s = 0; s < 8; s++) {
        const int slot = sl + s;
        sA += g_part[(size_t)(0 * NBLK + slot) * NB + row];
        sP += g_part[(size_t)(1 * NBLK + slot) * NB + row];
        pm  = fmaxf(pm, g_part[(size_t)(2 * NBLK + slot) * NB + row]);
        ins3(t0, t1, t2, g_part[(size_t)(3 * NBLK + slot) * NB + row]);
        ins3(t0, t1, t2, g_part[(size_t)(4 * NBLK + slot) * NB + row]);
        ins3(t0, t1, t2, g_part[(size_t)(5 * NBLK + slot) * NB + row]);
    }
    // merge 8 lanes sharing a row (lane bits 0-2)
    #pragma unroll
    for (int o = 1; o <= 4; o <<= 1) {
        sA += __shfl_xor_sync(0xffffffffu, sA, o);
        sP += __shfl_xor_sync(0xffffffffu, sP, o);
        pm  = fmaxf(pm, __shfl_xor_sync(0xffffffffu, pm, o));
        float o0 = __shfl_xor_sync(0xffffffffu, t0, o);
        float o1 = __shfl_xor_sync(0xffffffffu, t1, o);
        float o2 = __shfl_xor_sync(0xffffffffu, t2, o);
        ins3(t0, t1, t2, o0); ins3(t0, t1, t2, o1); ins3(t0, t1, t2, o2);
    }

    float basic = 0.f, h = 0.f, m = 0.f, hp = 0.f, v = 0.f;
    if ((threadIdx.x & 7) == 0 && pm > -1e29f) {
        hp = 1.f;
        basic = -logf(sP / (sA + 1e-10f) + 1e-10f);
        float pms   = pm * (1.f / TEMP);
        float mean3 = (t0 + t1 + t2) * (1.f / (3.f * TEMP));
        h = fmaxf(mean3 - pms + MRG, 0.f);
        if (t0 > -1e29f) {
            v = 1.f;
            m = fmaxf(t0 * (1.f / TEMP) - pms + MRG, 0.f);
        }
    }

    __shared__ float red[5][8];
    float vals[5] = {basic, h, m, hp, v};
    int lane = threadIdx.x & 31, warp = threadIdx.x >> 5;
    #pragma unroll
    for (int q = 0; q < 5; q++) {
        float x = vals[q];
        #pragma unroll
        for (int o = 16; o > 0; o >>= 1) x += __shfl_xor_sync(0xffffffffu, x, o);
        if (lane == 0) red[q][warp] = x;
    }
    __syncthreads();
    if (warp == 0 && lane == 0) {
        #pragma unroll
        for (int q = 0; q < 5; q++) {
            float x = 0.f;
            #pragma unroll
            for (int w = 0; w < 8; w++) x += red[q][w];
            g_blk[blockIdx.x * 5 + q] = x;
        }
    }
}

// ---------------------------------------------------------------------------
// Kernel 4: final scalar.
// ---------------------------------------------------------------------------
__global__ void kfin(float* __restrict__ out, int n) {
    int lane = threadIdx.x;   // 32 threads
    float acc[5];
    #pragma unroll
    for (int q = 0; q < 5; q++) {
        float x = 0.f;
        for (int i = lane; i < RED_BLOCKS; i += 32) x += g_blk[i * 5 + q];
        #pragma unroll
        for (int o = 16; o > 0; o >>= 1) x += __shfl_xor_sync(0xffffffffu, x, o);
        acc[q] = x;
    }
    float Bv = acc[0], Hv = acc[1], Mv = acc[2], HP = acc[3], V = acc[4];
    float n_hp = fmaxf(HP, 1.f);
    float n_v  = fmaxf(V, 1.f);
    float margin_loss = (V > 0.f) ? (Mv / n_v) : 0.f;
    float total = Bv / n_hp + 0.5f * (Hv / n_hp) + 0.1f * margin_loss;
    for (int i = lane; i < n; i += 32) out[i] = total;
}

// ---------------------------------------------------------------------------
extern "C" void kernel_launch(void* const* d_in, const int* in_sizes, int n_in,
                              void* d_out, int out_size) {
    const float* emb   = (const float*)d_in[0];
    const int*   lab32 = (const int*)d_in[1];
    (void)in_sizes; (void)n_in;

    cudaFuncSetAttribute(kmain, cudaFuncAttributeMaxDynamicSharedMemorySize, SMEM_TOTAL);

    klab<<<1, 256>>>(lab32);
    knorm<<<NB * 32 / 256, 256>>>(emb);
    kmain<<<NPAIR, NTHR, SMEM_TOTAL>>>();
    krow<<<RED_BLOCKS, 256>>>();
    kfin<<<1, 32>>>((float*)d_out, out_size);
}

// round 6
// speedup vs baseline: 5.3884x; 1.0609x over previous
#include <cuda_runtime.h>
#include <math.h>

// ---------------------------------------------------------------------------
// EnhancedContrastiveLoss — v6: symmetric-half tf32 mma.sync, 3-stage cp.async
// pipeline (single sync/chunk), task-parallel epilogue, diag A-aliasing.
// ---------------------------------------------------------------------------

namespace {
constexpr int   NB   = 8192;
constexpr int   ND   = 256;
constexpr float TEMP = 0.07f;
constexpr float MRG  = 0.2f;
constexpr float NEGINF = -1e30f;
constexpr float CEXP = 20.609929059847869f;   // log2(e)/TEMP

constexpr int NBLK  = NB / 128;               // 64 row-blocks
constexpr int NPAIR = NBLK * (NBLK + 1) / 2;  // 2080 CTAs
constexpr int NTHR  = 256;                    // 8 warps: 2(M) x 4(N)
constexpr int OST   = 36;                     // operand smem row stride (floats)
constexpr int DST   = 129;                    // D-tile smem row stride (floats)
constexpr int NSTAGE = 3;
constexpr int STGB  = 128 * OST * 4;          // 18432 B per operand-stage
constexpr int RED_BLOCKS = 256;

// dynamic smem layout (bytes)
constexpr int SM_OPA  = 0;                        // 3 x 18432 = 55296
constexpr int SM_OPB  = 55296;                    // 3 x 18432 = 55296
constexpr int SM_LABI = 110592;                   // 128 int
constexpr int SM_LABJ = 111104;                   // 128 int
constexpr int SMEM_TOTAL = 111616;
// post-GEMM overlays (operand region is dead then):
//   D tile 128x129 f32 = 66048 B at offset 0
//   task staging 512 x 6 f32 = 12288 B at offset 66560
constexpr int SM_STG  = 66560;
}

__device__ float g_en[NB * ND];                // normalized, tf32-rounded
__device__ int   g_lab[NB];
__device__ float g_part[6 * NBLK * NB];        // [q][slot][row]  (12.6 MB)
__device__ float g_blk[RED_BLOCKS * 5];

// ----------------------------- helpers ------------------------------------
__device__ __forceinline__ unsigned smem_u32(const void* p) {
    unsigned a;
    asm("{ .reg .u64 t; cvta.to.shared.u64 t, %1; cvt.u32.u64 %0, t; }" : "=r"(a) : "l"(p));
    return a;
}
__device__ __forceinline__ void cpasync16(unsigned dst, const void* src) {
    asm volatile("cp.async.cg.shared.global [%0], [%1], 16;" :: "r"(dst), "l"(src) : "memory");
}
#define CP_COMMIT() asm volatile("cp.async.commit_group;" ::: "memory")
#define CP_WAIT0()  asm volatile("cp.async.wait_group 0;"  ::: "memory")
#define CP_WAIT1()  asm volatile("cp.async.wait_group 1;"  ::: "memory")

__device__ __forceinline__ void mma_tf32(float c[4], const unsigned a[4], const unsigned b[2]) {
    asm volatile(
        "mma.sync.aligned.m16n8k8.row.col.f32.tf32.tf32.f32 "
        "{%0,%1,%2,%3}, {%4,%5,%6,%7}, {%8,%9}, {%0,%1,%2,%3};"
        : "+f"(c[0]), "+f"(c[1]), "+f"(c[2]), "+f"(c[3])
        : "r"(a[0]), "r"(a[1]), "r"(a[2]), "r"(a[3]), "r"(b[0]), "r"(b[1]));
}

__device__ __forceinline__ float ex2f(float x) {
    float y; asm("ex2.approx.f32 %0, %1;" : "=f"(y) : "f"(x)); return y;
}
__device__ __forceinline__ void ins3(float& t0, float& t1, float& t2, float x) {
    float m;
    m = fmaxf(t0, x); x = fminf(t0, x); t0 = m;
    m = fmaxf(t1, x); x = fminf(t1, x); t1 = m;
    t2 = fmaxf(t2, x);
}

// ---------------------------------------------------------------------------
// Kernel 0: label dtype normalize (int64 vs int32 auto-detect)
// ---------------------------------------------------------------------------
__global__ void klab(const int* __restrict__ lab32) {
    __shared__ int s_nz;
    if (threadIdx.x == 0) s_nz = 0;
    __syncthreads();
    int acc = 0;
    for (int i = threadIdx.x; i < NB / 2; i += blockDim.x) acc |= lab32[2 * i + 1];
    if (acc) atomicOr(&s_nz, 1);
    __syncthreads();
    const bool is64 = (s_nz == 0);
    for (int i = threadIdx.x; i < NB; i += blockDim.x)
        g_lab[i] = is64 ? lab32[2 * i] : lab32[i];
}

// ---------------------------------------------------------------------------
// Kernel 1: L2 normalize + round-to-nearest-tf32 (so HMMA truncation is exact)
// ---------------------------------------------------------------------------
__global__ void knorm(const float* __restrict__ emb) {
    int gw   = (blockIdx.x * blockDim.x + threadIdx.x) >> 5;
    int lane = threadIdx.x & 31;
    if (gw >= NB) return;
    const float4* src = reinterpret_cast<const float4*>(emb + (size_t)gw * ND);
    float4 v0 = src[lane * 2];
    float4 v1 = src[lane * 2 + 1];
    float ss = v0.x*v0.x + v0.y*v0.y + v0.z*v0.z + v0.w*v0.w
             + v1.x*v1.x + v1.y*v1.y + v1.z*v1.z + v1.w*v1.w;
    #pragma unroll
    for (int o = 16; o > 0; o >>= 1) ss += __shfl_xor_sync(0xffffffffu, ss, o);
    float inv = 1.0f / fmaxf(sqrtf(ss), 1e-12f);
    float f[8] = {v0.x*inv, v0.y*inv, v0.z*inv, v0.w*inv,
                  v1.x*inv, v1.y*inv, v1.z*inv, v1.w*inv};
    #pragma unroll
    for (int i = 0; i < 8; i++) {
        unsigned b;
        asm("cvt.rna.tf32.f32 %0, %1;" : "=r"(b) : "f"(f[i]));
        f[i] = __uint_as_float(b);
    }
    float4* dst = reinterpret_cast<float4*>(g_en + (size_t)gw * ND);
    dst[lane * 2]     = make_float4(f[0], f[1], f[2], f[3]);
    dst[lane * 2 + 1] = make_float4(f[4], f[5], f[6], f[7]);
}

// ---------------------------------------------------------------------------
// Kernel 2: symmetric-half tf32 GEMM + two-view fused epilogue.
// Grid: 2080 CTAs (one 128x128 block (I,J), I<=J each). 256 threads.
// Both operands streamed, 3-stage pipeline, one __syncthreads per chunk.
// ---------------------------------------------------------------------------
__global__ void __launch_bounds__(NTHR, 2) kmain() {
    extern __shared__ char smem[];
    float* OpA  = (float*)(smem + SM_OPA);
    float* OpB  = (float*)(smem + SM_OPB);
    float* Ds   = (float*)smem;                 // overlays operands post-GEMM
    float* stg  = (float*)(smem + SM_STG);
    int*   labI = (int*)(smem + SM_LABI);
    int*   labJ = (int*)(smem + SM_LABJ);
    const unsigned sbA = smem_u32(OpA), sbB = smem_u32(OpB);

    const int tid   = threadIdx.x;
    const int lane  = tid & 31;
    const int wid   = tid >> 5;
    const int warpM = wid >> 2;          // 0..1
    const int warpN = wid & 3;           // 0..3
    const int qrow  = lane >> 2;         // 0..7
    const int qcol  = lane & 3;          // 0..3

    // map linear block id -> (I, J), I <= J
    int I = 0, rem = blockIdx.x;
    while (rem >= NBLK - I) { rem -= NBLK - I; I++; }
    const int J = I + rem;
    const int rowI = I * 128, rowJ = J * 128;
    const bool diag = (I == J);

    // labels into smem
    if (tid < 128) labI[tid] = g_lab[rowI + tid];
    else           labJ[tid - 128] = g_lab[rowJ + tid - 128];

    // chunk issue into stage g%3 (diag: A only, B aliases A)
    auto issue = [&](int g) {
        const int stage = g % NSTAGE;
        const int kc = g * 32;
        #pragma unroll
        for (int q = 0; q < 4; q++) {
            int idx = tid + q * NTHR;        // 0..1023
            int r = idx >> 3, f = (idx & 7) * 4;
            unsigned off = (unsigned)((stage * 128 + r) * OST + f) * 4u;
            cpasync16(sbA + off, g_en + (size_t)(rowI + r) * ND + kc + f);
            if (!diag)
                cpasync16(sbB + off, g_en + (size_t)(rowJ + r) * ND + kc + f);
        }
        CP_COMMIT();
    };

    float acc[4][4][4];
    #pragma unroll
    for (int i = 0; i < 4; i++)
        #pragma unroll
        for (int j = 0; j < 4; j++)
            #pragma unroll
            for (int c = 0; c < 4; c++) acc[i][j][c] = 0.f;

    issue(0); issue(1);

    for (int g = 0; g < 8; g++) {
        if (g < 7) CP_WAIT1();               // chunk g landed (g+1 may fly)
        else       CP_WAIT0();
        __syncthreads();                     // all warps done with chunk g-1
        if (g + 2 < 8) issue(g + 2);         // overwrites stage (g-1)%3: safe

        const int stage = g % NSTAGE;
        const float* Apan = OpA + stage * 128 * OST;
        const float* Bpan = diag ? Apan : OpB + stage * 128 * OST;
        #pragma unroll
        for (int ks = 0; ks < 4; ks++) {
            const int kb = ks * 8;
            unsigned a[4][4], b[4][2];
            #pragma unroll
            for (int i = 0; i < 4; i++) {
                const float* ap = Apan + (size_t)(warpM * 64 + i * 16 + qrow) * OST + kb + qcol;
                a[i][0] = __float_as_uint(ap[0]);
                a[i][1] = __float_as_uint(ap[8 * OST]);
                a[i][2] = __float_as_uint(ap[4]);
                a[i][3] = __float_as_uint(ap[8 * OST + 4]);
            }
            #pragma unroll
            for (int j = 0; j < 4; j++) {
                const float* bp = Bpan + (size_t)(warpN * 32 + j * 8 + qrow) * OST + kb + qcol;
                b[j][0] = __float_as_uint(bp[0]);
                b[j][1] = __float_as_uint(bp[4]);
            }
            #pragma unroll
            for (int i = 0; i < 4; i++)
                #pragma unroll
                for (int j = 0; j < 4; j++)
                    mma_tf32(acc[i][j], a[i], b[j]);
        }
    }
    __syncthreads();                         // GEMM done; operand smem now dead

    // ---- stage D into smem (stride 129) ----
    #pragma unroll
    for (int i = 0; i < 4; i++) {
        #pragma unroll
        for (int j = 0; j < 4; j++) {
            const int rl0 = warpM * 64 + i * 16 + qrow;
            const int cl0 = warpN * 32 + j * 8 + 2 * qcol;
            Ds[(size_t)rl0 * DST + cl0]           = acc[i][j][0];
            Ds[(size_t)rl0 * DST + cl0 + 1]       = acc[i][j][1];
            Ds[(size_t)(rl0 + 8) * DST + cl0]     = acc[i][j][2];
            Ds[(size_t)(rl0 + 8) * DST + cl0 + 1] = acc[i][j][3];
        }
    }
    __syncthreads();

    // ---- task-parallel epilogue: 512 tasks = {view, half, idx} ----
    // view 0: rows of I scanning cols (slot J). view 1: cols (rows of J, slot I).
    // Diagonal blocks: only view 0 (256 tasks, one round).
    const int rounds = diag ? 1 : 2;
    for (int rr = 0; rr < rounds; rr++) {
        const int tau  = tid + rr * 256;
        const int view = tau >> 8;
        const int half = (tau >> 7) & 1;
        const int idx  = tau & 127;
        float sA = 0.f, sP = 0.f, pm = NEGINF;
        float t0 = NEGINF, t1 = NEGINF, t2 = NEGINF;
        if (view == 0) {
            const int lr = labI[idx];
            const float* dr = Ds + (size_t)idx * DST + half * 64;
            #pragma unroll 4
            for (int c = 0; c < 64; c++) {
                float d = dr[c];
                const int col = half * 64 + c;
                if (!(diag && col == idx)) {
                    float E = ex2f(d * CEXP);
                    sA += E;
                    if (lr == labJ[col]) { sP += E; pm = fmaxf(pm, d); }
                    else ins3(t0, t1, t2, d);
                }
            }
        } else {
            const int lc = labJ[idx];
            #pragma unroll 4
            for (int r = 0; r < 64; r++) {
                float d = Ds[(size_t)(half * 64 + r) * DST + idx];
                float E = ex2f(d * CEXP);
                sA += E;
                if (lc == labI[half * 64 + r]) { sP += E; pm = fmaxf(pm, d); }
                else ins3(t0, t1, t2, d);
            }
        }
        float* p = stg + (size_t)tau * 6;
        p[0] = sA; p[1] = sP; p[2] = pm; p[3] = t0; p[4] = t1; p[5] = t2;
    }
    __syncthreads();

    // ---- merge halves and write g_part ----
    if (tid < 128 || !diag) {
        const int view = tid >> 7;
        const int idx  = tid & 127;
        const float* p0 = stg + (size_t)(view * 256 + idx) * 6;
        const float* p1 = p0 + 128 * 6;
        float sA = p0[0] + p1[0];
        float sP = p0[1] + p1[1];
        float pm = fmaxf(p0[2], p1[2]);
        float t0 = p0[3], t1 = p0[4], t2 = p0[5];
        ins3(t0, t1, t2, p1[3]); ins3(t0, t1, t2, p1[4]); ins3(t0, t1, t2, p1[5]);
        const int slot = view ? I : J;
        const int grow = (view ? rowJ : rowI) + idx;
        g_part[(size_t)(0 * NBLK + slot) * NB + grow] = sA;
        g_part[(size_t)(1 * NBLK + slot) * NB + grow] = sP;
        g_part[(size_t)(2 * NBLK + slot) * NB + grow] = pm;
        g_part[(size_t)(3 * NBLK + slot) * NB + grow] = t0;
        g_part[(size_t)(4 * NBLK + slot) * NB + grow] = t1;
        g_part[(size_t)(5 * NBLK + slot) * NB + grow] = t2;
    }
}

// ---------------------------------------------------------------------------
// Kernel 3: per-row merge of 64 slot partials (8 threads/row) + loss terms.
// ---------------------------------------------------------------------------
__global__ void krow() {
    const int gid = blockIdx.x * blockDim.x + threadIdx.x;
    const int row = gid >> 3;
    const int sl  = (gid & 7) * 8;
    float sA = 0.f, sP = 0.f, pm = NEGINF;
    float t0 = NEGINF, t1 = NEGINF, t2 = NEGINF;
    #pragma unroll
    for (int s = 0; s < 8; s++) {
        const int slot = sl + s;
        sA += g_part[(size_t)(0 * NBLK + slot) * NB + row];
        sP += g_part[(size_t)(1 * NBLK + slot) * NB + row];
        pm  = fmaxf(pm, g_part[(size_t)(2 * NBLK + slot) * NB + row]);
        ins3(t0, t1, t2, g_part[(size_t)(3 * NBLK + slot) * NB + row]);
        ins3(t0, t1, t2, g_part[(size_t)(4 * NBLK + slot) * NB + row]);
        ins3(t0, t1, t2, g_part[(size_t)(5 * NBLK + slot) * NB + row]);
    }
    #pragma unroll
    for (int o = 1; o <= 4; o <<= 1) {
        sA += __shfl_xor_sync(0xffffffffu, sA, o);
        sP += __shfl_xor_sync(0xffffffffu, sP, o);
        pm  = fmaxf(pm, __shfl_xor_sync(0xffffffffu, pm, o));
        float o0 = __shfl_xor_sync(0xffffffffu, t0, o);
        float o1 = __shfl_xor_sync(0xffffffffu, t1, o);
        float o2 = __shfl_xor_sync(0xffffffffu, t2, o);
        ins3(t0, t1, t2, o0); ins3(t0, t1, t2, o1); ins3(t0, t1, t2, o2);
    }

    float basic = 0.f, h = 0.f, m = 0.f, hp = 0.f, v = 0.f;
    if ((threadIdx.x & 7) == 0 && pm > -1e29f) {
        hp = 1.f;
        basic = -logf(sP / (sA + 1e-10f) + 1e-10f);
        float pms   = pm * (1.f / TEMP);
        float mean3 = (t0 + t1 + t2) * (1.f / (3.f * TEMP));
        h = fmaxf(mean3 - pms + MRG, 0.f);
        if (t0 > -1e29f) {
            v = 1.f;
            m = fmaxf(t0 * (1.f / TEMP) - pms + MRG, 0.f);
        }
    }

    __shared__ float red[5][8];
    float vals[5] = {basic, h, m, hp, v};
    int lane = threadIdx.x & 31, warp = threadIdx.x >> 5;
    #pragma unroll
    for (int q = 0; q < 5; q++) {
        float x = vals[q];
        #pragma unroll
        for (int o = 16; o > 0; o >>= 1) x += __shfl_xor_sync(0xffffffffu, x, o);
        if (lane == 0) red[q][warp] = x;
    }
    __syncthreads();
    if (warp == 0 && lane == 0) {
        #pragma unroll
        for (int q = 0; q < 5; q++) {
            float x = 0.f;
            #pragma unroll
            for (int w = 0; w < 8; w++) x += red[q][w];
            g_blk[blockIdx.x * 5 + q] = x;
        }
    }
}

// ---------------------------------------------------------------------------
// Kernel 4: final scalar.
// ---------------------------------------------------------------------------
__global__ void kfin(float* __restrict__ out, int n) {
    int lane = threadIdx.x;   // 32 threads
    float acc[5];
    #pragma unroll
    for (int q = 0; q < 5; q++) {
        float x = 0.f;
        for (int i = lane; i < RED_BLOCKS; i += 32) x += g_blk[i * 5 + q];
        #pragma unroll
        for (int o = 16; o > 0; o >>= 1) x += __shfl_xor_sync(0xffffffffu, x, o);
        acc[q] = x;
    }
    float Bv = acc[0], Hv = acc[1], Mv = acc[2], HP = acc[3], V = acc[4];
    float n_hp = fmaxf(HP, 1.f);
    float n_v  = fmaxf(V, 1.f);
    float margin_loss = (V > 0.f) ? (Mv / n_v) : 0.f;
    float total = Bv / n_hp + 0.5f * (Hv / n_hp) + 0.1f * margin_loss;
    for (int i = lane; i < n; i += 32) out[i] = total;
}

// ---------------------------------------------------------------------------
extern "C" void kernel_launch(void* const* d_in, const int* in_sizes, int n_in,
                              void* d_out, int out_size) {
    const float* emb   = (const float*)d_in[0];
    const int*   lab32 = (const int*)d_in[1];
    (void)in_sizes; (void)n_in;

    cudaFuncSetAttribute(kmain, cudaFuncAttributeMaxDynamicSharedMemorySize, SMEM_TOTAL);

    klab<<<1, 256>>>(lab32);
    knorm<<<NB * 32 / 256, 256>>>(emb);
    kmain<<<NPAIR, NTHR, SMEM_TOTAL>>>();
    krow<<<RED_BLOCKS, 256>>>();
    kfin<<<1, 32>>>((float*)d_out, out_size);
}